// round 3
// baseline (speedup 1.0000x reference)
#include <cuda_runtime.h>
#include <math.h>

#define Bdim 64
#define Tdim 512
#define Idim 512
#define Hdim 1024
#define Sdim 512
#define R4   4096   // 4 gates * H
#define KSPLIT 8
#define NBLK 128    // persistent blocks (<=148 SMs, occupancy-1 guaranteed)

typedef unsigned long long u64;

// Scratch (static device memory; no runtime allocations)
__device__ float g_xproj[(size_t)Tdim * R4 * Bdim];   // [t][r][b]
__device__ float g_partial[KSPLIT * R4 * Bdim];       // [ks][r][b]
__device__ float g_h[2][Hdim * Bdim];                 // [k][b] double buffer
__device__ float g_c[Hdim * Bdim];                    // [j][b]
__device__ unsigned g_count;
__device__ unsigned g_gen;

// ---------------- packed fp32 helpers (Blackwell FFMA2) --------------------
__device__ __forceinline__ void ffma2(u64 &d, u64 a, u64 b) {
    asm("fma.rn.f32x2 %0, %1, %2, %3;" : "=l"(d) : "l"(a), "l"(b), "l"(d));
}
__device__ __forceinline__ float2 u2f2(u64 v) {
    float2 r; asm("mov.b64 {%0,%1}, %2;" : "=f"(r.x), "=f"(r.y) : "l"(v)); return r;
}

// ---------------------------------------------------------------------------
// init: zero h0, c0 and barrier state (deterministic across graph replays)
// ---------------------------------------------------------------------------
__global__ void init_kernel() {
    int i = blockIdx.x * blockDim.x + threadIdx.x;
    if (i < Hdim * Bdim) {
        g_h[0][i] = 0.0f;
        g_c[i]    = 0.0f;
    }
    if (i == 0) { g_count = 0u; g_gen = 0u; }
}

// ---------------------------------------------------------------------------
// Phase 1: xproj[t][r][b] = b_g[j] + sum_k x[b][t][k] * W_g[j][1024+k]
// Block tile 128 rows x 128 cols (2 timesteps), K=512. FFMA2 inner loop.
// ---------------------------------------------------------------------------
__global__ void __launch_bounds__(256, 1)
xproj_kernel(const float* __restrict__ x,
             const float* __restrict__ Wf, const float* __restrict__ bf,
             const float* __restrict__ Wi, const float* __restrict__ bi,
             const float* __restrict__ Wc, const float* __restrict__ bc,
             const float* __restrict__ Wo, const float* __restrict__ bo)
{
    __shared__ float As2[16][264];  // duplicated rows: 128*2 = 256 (+8 pad)
    __shared__ float Bs[16][132];   // [k][col]

    const int cb  = blockIdx.x;          // 0..255
    const int rb  = blockIdx.y;          // 0..31
    const int tid = threadIdx.x;
    const int tx  = tid & 15;            // col group (8 cols)
    const int ty  = tid >> 4;            // row group (8 rows)

    const int g  = (rb * 128) >> 10;
    const int j0 = (rb * 128) & 1023;
    const float* __restrict__ W    = (g == 0) ? Wf : (g == 1) ? Wi : (g == 2) ? Wc : Wo;
    const float* __restrict__ bias = (g == 0) ? bf : (g == 1) ? bi : (g == 2) ? bc : bo;

    u64 acc[8][4];
#pragma unroll
    for (int i = 0; i < 8; i++)
#pragma unroll
        for (int j = 0; j < 4; j++) acc[i][j] = 0ull;

    for (int k0 = 0; k0 < Idim; k0 += 16) {
        // A (weights, x-part): 128 rows x 16 k, stored duplicated {v,v}
#pragma unroll
        for (int i2 = 0; i2 < 2; i2++) {
            int e  = tid + i2 * 256;          // 0..511
            int rl = e >> 2;                  // 0..127
            int kq = (e & 3) * 4;
            float4 v = *(const float4*)&W[(size_t)(j0 + rl) * 1536 + 1024 + k0 + kq];
            *(float2*)&As2[kq + 0][rl * 2] = make_float2(v.x, v.x);
            *(float2*)&As2[kq + 1][rl * 2] = make_float2(v.y, v.y);
            *(float2*)&As2[kq + 2][rl * 2] = make_float2(v.z, v.z);
            *(float2*)&As2[kq + 3][rl * 2] = make_float2(v.w, v.w);
        }
        // B (x): 128 cols x 16 k
#pragma unroll
        for (int i2 = 0; i2 < 2; i2++) {
            int e  = tid + i2 * 256;
            int cc = e >> 2;
            int kq = (e & 3) * 4;
            int c  = cb * 128 + cc;
            int t  = c >> 6, b = c & 63;
            float4 v = *(const float4*)&x[((size_t)b * Tdim + t) * Idim + k0 + kq];
            Bs[kq + 0][cc] = v.x; Bs[kq + 1][cc] = v.y;
            Bs[kq + 2][cc] = v.z; Bs[kq + 3][cc] = v.w;
        }
        __syncthreads();

#pragma unroll
        for (int kk = 0; kk < 16; kk++) {
            u64 a2[8], b2[4];
#pragma unroll
            for (int ii = 0; ii < 8; ii++)
                a2[ii] = *(const u64*)&As2[kk][(ty * 8 + ii) * 2];
#pragma unroll
            for (int jp = 0; jp < 4; jp++)
                b2[jp] = *(const u64*)&Bs[kk][tx * 8 + jp * 2];
#pragma unroll
            for (int ii = 0; ii < 8; ii++)
#pragma unroll
                for (int jp = 0; jp < 4; jp++)
                    ffma2(acc[ii][jp], a2[ii], b2[jp]);
        }
        __syncthreads();
    }

    // epilogue: + bias, write xproj[t][r][b]
    const int c0 = cb * 128 + tx * 8;   // 8 cols share one t
    const int t  = c0 >> 6;
    const int b0 = c0 & 63;
#pragma unroll
    for (int ii = 0; ii < 8; ii++) {
        int r  = rb * 128 + ty * 8 + ii;
        float bv = bias[j0 + ty * 8 + ii];
        float2 p0 = u2f2(acc[ii][0]), p1 = u2f2(acc[ii][1]);
        float2 p2 = u2f2(acc[ii][2]), p3 = u2f2(acc[ii][3]);
        float* p = &g_xproj[((size_t)t * R4 + r) * Bdim + b0];
        float4 v0 = {p0.x + bv, p0.y + bv, p1.x + bv, p1.y + bv};
        float4 v1 = {p2.x + bv, p2.y + bv, p3.x + bv, p3.y + bv};
        *(float4*)p       = v0;
        *(float4*)(p + 4) = v1;
    }
}

// ---------------------------------------------------------------------------
// Persistent recurrence kernel: 128 blocks, loops over all 512 timesteps.
// Grid-wide software barrier (all blocks co-resident at occupancy 1).
// ---------------------------------------------------------------------------
__device__ __forceinline__ void gridbar(unsigned &gen) {
    __syncthreads();
    if (threadIdx.x == 0) {
        __threadfence();
        if (atomicAdd(&g_count, 1u) == NBLK - 1) {
            g_count = 0u;
            __threadfence();
            atomicExch(&g_gen, gen + 1u);
        } else {
            while (*((volatile unsigned*)&g_gen) == gen) { }
        }
        __threadfence();
    }
    gen++;
    __syncthreads();
}

__global__ void __launch_bounds__(256, 1)
recur_kernel(const float* __restrict__ Wf, const float* __restrict__ Wi,
             const float* __restrict__ Wc, const float* __restrict__ Wo)
{
    __shared__ float As2[16][528];   // duplicated rows: 256*2 = 512 (+16 pad)
    __shared__ float Bs[16][64];     // [k][b]

    const int bid = blockIdx.x;      // 0..127
    const int ks  = bid & 7;         // k-split 0..7
    const int rb  = bid >> 3;        // row block 0..15 (one gate each)
    const int tid = threadIdx.x;
    const int tx  = tid & 7;         // b group (8)
    const int ty  = tid >> 3;        // row group (8)

    const int g  = rb >> 2;
    const int j0 = (rb & 3) * 256;
    const float* __restrict__ W = (g == 0) ? Wf : (g == 1) ? Wi : (g == 2) ? Wc : Wo;
    const int kbase = ks * 128;

    unsigned gen = 0u;

    for (int t = 0; t < Tdim; t++) {
        // ============ per-step GEMM: partial[ks][r][b] ============
        const float* __restrict__ hprev = g_h[t & 1];

        u64 acc[8][4];
#pragma unroll
        for (int i = 0; i < 8; i++)
#pragma unroll
            for (int j = 0; j < 4; j++) acc[i][j] = 0ull;

        for (int k0 = 0; k0 < 128; k0 += 16) {
            // A (weights, h-part): 256 rows x 16 k, duplicated pairs
#pragma unroll
            for (int i2 = 0; i2 < 4; i2++) {
                int e  = tid + i2 * 256;          // 0..1023
                int rl = e >> 2;                  // 0..255
                int kq = (e & 3) * 4;
                float4 v = *(const float4*)&W[(size_t)(j0 + rl) * 1536 + kbase + k0 + kq];
                *(float2*)&As2[kq + 0][rl * 2] = make_float2(v.x, v.x);
                *(float2*)&As2[kq + 1][rl * 2] = make_float2(v.y, v.y);
                *(float2*)&As2[kq + 2][rl * 2] = make_float2(v.z, v.z);
                *(float2*)&As2[kq + 3][rl * 2] = make_float2(v.w, v.w);
            }
            // B (h_prev [k][b]): bypass L1 (written by other blocks last step)
            {
                int kk = tid >> 4;                // 0..15
                int b4 = (tid & 15) * 4;
                float4 hv = __ldcg((const float4*)&hprev[(kbase + k0 + kk) * Bdim + b4]);
                *(float4*)&Bs[kk][b4] = hv;
            }
            __syncthreads();

#pragma unroll
            for (int kk = 0; kk < 16; kk++) {
                u64 a2[8], b2[4];
#pragma unroll
                for (int ii = 0; ii < 8; ii++)
                    a2[ii] = *(const u64*)&As2[kk][(ty * 8 + ii) * 2];
#pragma unroll
                for (int jp = 0; jp < 4; jp++)
                    b2[jp] = *(const u64*)&Bs[kk][tx * 8 + jp * 2];
#pragma unroll
                for (int ii = 0; ii < 8; ii++)
#pragma unroll
                    for (int jp = 0; jp < 4; jp++)
                        ffma2(acc[ii][jp], a2[ii], b2[jp]);
            }
            __syncthreads();
        }

#pragma unroll
        for (int ii = 0; ii < 8; ii++) {
            int r = rb * 256 + ty * 8 + ii;
            float2 p0 = u2f2(acc[ii][0]), p1 = u2f2(acc[ii][1]);
            float2 p2 = u2f2(acc[ii][2]), p3 = u2f2(acc[ii][3]);
            float* p = &g_partial[((size_t)ks * R4 + r) * Bdim + tx * 8];
            float4 v0 = {p0.x, p0.y, p1.x, p1.y};
            float4 v1 = {p2.x, p2.y, p3.x, p3.y};
            *(float4*)p       = v0;
            *(float4*)(p + 4) = v1;
        }

        gridbar(gen);

        // ============ reduce + gates + state update ============
#pragma unroll
        for (int rep = 0; rep < 2; rep++) {
            int gi = bid * 256 + tid + rep * (NBLK * 256);   // 0..65535
            int b  = gi & 63;
            int j  = gi >> 6;

            float pre[4];
#pragma unroll
            for (int g4 = 0; g4 < 4; g4++) {
                int r = g4 * 1024 + j;
                float s = __ldg(&g_xproj[((size_t)t * R4 + r) * Bdim + b]);
#pragma unroll
                for (int k2 = 0; k2 < KSPLIT; k2++)
                    s += __ldcg(&g_partial[((size_t)k2 * R4 + r) * Bdim + b]);
                pre[g4] = s;
            }

            float f  = 1.0f / (1.0f + __expf(-pre[0]));
            float ig = 1.0f / (1.0f + __expf(-pre[1]));
            float ct = tanhf(pre[2]);
            float o  = 1.0f / (1.0f + __expf(-pre[3]));

            float c = f * g_c[j * Bdim + b] + ig * ct;
            g_c[j * Bdim + b] = c;
            g_h[(t + 1) & 1][j * Bdim + b] = o * tanhf(c);
        }

        gridbar(gen);
    }
}

// ---------------------------------------------------------------------------
// Final FC: out[b][s] = sum_k h_T[k][b] * fc_w[s][k] + fc_b[s]
// ---------------------------------------------------------------------------
__global__ void __launch_bounds__(512)
fc_kernel(const float* __restrict__ fc_w, const float* __restrict__ fc_b,
          float* __restrict__ out)
{
    __shared__ float hs[128 * 64];   // 32 KB
    __shared__ float ws[8 * 128];    // 4 KB

    const float* __restrict__ hT = g_h[Tdim & 1];  // = g_h[0]
    int tid = threadIdx.x;
    int b   = tid & 63;
    int sl  = tid >> 6;                      // 0..7
    int s   = blockIdx.x * 8 + sl;

    float acc = 0.0f;
    for (int k0 = 0; k0 < Hdim; k0 += 128) {
        __syncthreads();
#pragma unroll
        for (int i2 = 0; i2 < 4; i2++) {
            int e = tid + i2 * 512;          // 0..2047 float4s
            *(float4*)&hs[e * 4] = *(const float4*)&hT[k0 * Bdim + e * 4];
        }
#pragma unroll
        for (int i2 = 0; i2 < 2; i2++) {
            int e    = tid + i2 * 512;       // 0..1023
            int srow = e >> 7, kk = e & 127;
            ws[srow * 128 + kk] = fc_w[(size_t)(blockIdx.x * 8 + srow) * Hdim + k0 + kk];
        }
        __syncthreads();
#pragma unroll 16
        for (int kk = 0; kk < 128; kk++)
            acc += hs[kk * 64 + b] * ws[sl * 128 + kk];
    }
    out[b * Sdim + s] = acc + fc_b[s];
}

// ---------------------------------------------------------------------------
extern "C" void kernel_launch(void* const* d_in, const int* in_sizes, int n_in,
                              void* d_out, int out_size)
{
    const float* x   = (const float*)d_in[0];
    const float* Wf  = (const float*)d_in[1];
    const float* bf  = (const float*)d_in[2];
    const float* Wi  = (const float*)d_in[3];
    const float* bi  = (const float*)d_in[4];
    const float* Wc  = (const float*)d_in[5];
    const float* bc  = (const float*)d_in[6];
    const float* Wo  = (const float*)d_in[7];
    const float* bo  = (const float*)d_in[8];
    const float* fcw = (const float*)d_in[9];
    const float* fcb = (const float*)d_in[10];
    float* out = (float*)d_out;

    init_kernel<<<(Hdim * Bdim + 255) / 256, 256>>>();

    dim3 gx(256, 32);
    xproj_kernel<<<gx, 256>>>(x, Wf, bf, Wi, bi, Wc, bc, Wo, bo);

    recur_kernel<<<NBLK, 256>>>(Wf, Wi, Wc, Wo);

    fc_kernel<<<64, 512>>>(fcw, fcb, out);
}

// round 6
// speedup vs baseline: 1.9470x; 1.9470x over previous
#include <cuda_runtime.h>
#include <cuda_bf16.h>
#include <math.h>
#include <stdint.h>

#define Bdim 64
#define Tdim 512
#define Idim 512
#define Hdim 1024
#define Sdim 512
#define R4   4096
#define KSPLIT 4
#define NBLK 128     // persistent blocks (<=148 SMs)

typedef unsigned long long u64;
typedef unsigned int u32;

// ---------------- static device scratch ------------------------------------
__device__ float g_xproj[(size_t)Tdim * R4 * Bdim];   // [t][r][b], r = gate*1024+j
__device__ uint4 g_Wfrag[2 * 256 * 64 * 32];          // [term][rowtile][ktile][lane]
__device__ __nv_bfloat16 g_hfrag[2][2][64 * 1024];    // [buf][term][(kt*64+n)*16+k]
__device__ float g_partial[(size_t)KSPLIT * R4 * Bdim];
__device__ float g_h[Hdim * Bdim];                    // final h, [j][b]
__device__ unsigned g_count, g_gen;

// ---------------- helpers ---------------------------------------------------
__device__ __forceinline__ u32 s2u(const void* p) {
    u32 a;
    asm("{ .reg .u64 t; cvta.to.shared.u64 t, %1; cvt.u32.u64 %0, t; }"
        : "=r"(a) : "l"(p));
    return a;
}
__device__ __forceinline__ void cpa16(u32 dst, const void* src) {
    asm volatile("cp.async.cg.shared.global [%0], [%1], 16;"
                 :: "r"(dst), "l"(src) : "memory");
}
__device__ __forceinline__ void cpa_commit() {
    asm volatile("cp.async.commit_group;" ::: "memory");
}
template<int N> __device__ __forceinline__ void cpa_wait() {
    asm volatile("cp.async.wait_group %0;" :: "n"(N) : "memory");
}

#define MMA(c, a, b0, b1)                                                    \
    asm volatile("mma.sync.aligned.m16n8k16.row.col.f32.bf16.bf16.f32 "      \
        "{%0,%1,%2,%3}, {%4,%5,%6,%7}, {%8,%9}, {%0,%1,%2,%3};"              \
        : "+f"((c)[0]), "+f"((c)[1]), "+f"((c)[2]), "+f"((c)[3])             \
        : "r"((a).x), "r"((a).y), "r"((a).z), "r"((a).w), "r"(b0), "r"(b1))

// ---------------------------------------------------------------------------
__global__ void init_kernel() {
    int i = blockIdx.x * blockDim.x + threadIdx.x;
    if (i < 64 * 1024) {
        __nv_bfloat16 z = __float2bfloat16(0.0f);
        g_hfrag[0][0][i] = z; g_hfrag[0][1][i] = z;
        g_hfrag[1][0][i] = z; g_hfrag[1][1][i] = z;
    }
    if (i == 0) { g_count = 0u; g_gen = 0u; }
}

// ---------------------------------------------------------------------------
// Pre-pack W_h (cols 0..1023, rows R = gate*1024+j) into mma A-fragment order:
// g_Wfrag[term][rt = R/16][ktile][lane] = uint4 {a0,a1,a2,a3} (bf16x2 each).
// ---------------------------------------------------------------------------
__device__ __forceinline__ u32 pk2(float w0, float w1, int term) {
    __nv_bfloat16 h0 = __float2bfloat16(w0), h1 = __float2bfloat16(w1);
    if (term) {
        h0 = __float2bfloat16(w0 - __bfloat162float(h0));
        h1 = __float2bfloat16(w1 - __bfloat162float(h1));
    }
    u32 lo = (u32)*(unsigned short*)&h0;
    u32 hi = (u32)*(unsigned short*)&h1;
    return (hi << 16) | lo;
}

__global__ void prepack_kernel(const float* __restrict__ Wf, const float* __restrict__ Wi,
                               const float* __restrict__ Wc, const float* __restrict__ Wo)
{
    int idx = blockIdx.x * 256 + threadIdx.x;       // 0 .. 2*256*64*32-1
    int term = idx >> 19;
    int q    = idx & 0x7FFFF;
    int rt   = q >> 11;                             // 0..255
    int kt   = (q >> 5) & 63;                       // 0..63
    int lane = q & 31;
    int g = lane >> 2, tg = lane & 3;

    int R0   = rt * 16 + g;
    int gate = R0 >> 10;
    int j    = R0 & 1023;
    const float* W = (gate == 0) ? Wf : (gate == 1) ? Wi : (gate == 2) ? Wc : Wo;
    const float* r0 = W + (size_t)j * 1536;         // h-part = cols 0..1023
    const float* r1 = W + (size_t)(j + 8) * 1536;
    int k0 = kt * 16 + tg * 2;

    uint4 v;
    v.x = pk2(r0[k0],     r0[k0 + 1], term);
    v.y = pk2(r1[k0],     r1[k0 + 1], term);
    v.z = pk2(r0[k0 + 8], r0[k0 + 9], term);
    v.w = pk2(r1[k0 + 8], r1[k0 + 9], term);
    g_Wfrag[idx] = v;
}

// ---------------------------------------------------------------------------
// Phase 1 (R1-proven, fp32): xproj[t][r][b] = b_g[j] + sum_k x[b][t][k]*W_g[j][1024+k]
// ---------------------------------------------------------------------------
__global__ void __launch_bounds__(256, 1)
xproj_kernel(const float* __restrict__ x,
             const float* __restrict__ Wf, const float* __restrict__ bf,
             const float* __restrict__ Wi, const float* __restrict__ bi,
             const float* __restrict__ Wc, const float* __restrict__ bc,
             const float* __restrict__ Wo, const float* __restrict__ bo)
{
    __shared__ float As[16][132];
    __shared__ float Bs[16][132];

    const int cb  = blockIdx.x;
    const int rb  = blockIdx.y;
    const int tid = threadIdx.x;
    const int tx  = tid & 15;
    const int ty  = tid >> 4;

    const int g  = (rb * 128) >> 10;
    const int j0 = (rb * 128) & 1023;
    const float* __restrict__ W    = (g == 0) ? Wf : (g == 1) ? Wi : (g == 2) ? Wc : Wo;
    const float* __restrict__ bias = (g == 0) ? bf : (g == 1) ? bi : (g == 2) ? bc : bo;

    float acc[8][8];
#pragma unroll
    for (int i = 0; i < 8; i++)
#pragma unroll
        for (int j = 0; j < 8; j++) acc[i][j] = 0.0f;

    for (int k0 = 0; k0 < Idim; k0 += 16) {
#pragma unroll
        for (int i2 = 0; i2 < 2; i2++) {
            int e  = tid + i2 * 256;
            int rl = e >> 2;
            int kq = (e & 3) * 4;
            float4 v = *(const float4*)&W[(size_t)(j0 + rl) * 1536 + 1024 + k0 + kq];
            As[kq + 0][rl] = v.x; As[kq + 1][rl] = v.y;
            As[kq + 2][rl] = v.z; As[kq + 3][rl] = v.w;
        }
#pragma unroll
        for (int i2 = 0; i2 < 2; i2++) {
            int e  = tid + i2 * 256;
            int cc = e >> 2;
            int kq = (e & 3) * 4;
            int c  = cb * 128 + cc;
            int t  = c >> 6, b = c & 63;
            float4 v = *(const float4*)&x[((size_t)b * Tdim + t) * Idim + k0 + kq];
            Bs[kq + 0][cc] = v.x; Bs[kq + 1][cc] = v.y;
            Bs[kq + 2][cc] = v.z; Bs[kq + 3][cc] = v.w;
        }
        __syncthreads();

#pragma unroll
        for (int kk = 0; kk < 16; kk++) {
            float4 a0 = *(const float4*)&As[kk][ty * 8];
            float4 a1 = *(const float4*)&As[kk][ty * 8 + 4];
            float4 b0 = *(const float4*)&Bs[kk][tx * 8];
            float4 b1 = *(const float4*)&Bs[kk][tx * 8 + 4];
            float a[8]  = {a0.x, a0.y, a0.z, a0.w, a1.x, a1.y, a1.z, a1.w};
            float bb[8] = {b0.x, b0.y, b0.z, b0.w, b1.x, b1.y, b1.z, b1.w};
#pragma unroll
            for (int ii = 0; ii < 8; ii++)
#pragma unroll
                for (int jj = 0; jj < 8; jj++)
                    acc[ii][jj] += a[ii] * bb[jj];
        }
        __syncthreads();
    }

    const int c0 = cb * 128 + tx * 8;
    const int t  = c0 >> 6;
    const int b0 = c0 & 63;
#pragma unroll
    for (int ii = 0; ii < 8; ii++) {
        int r  = rb * 128 + ty * 8 + ii;
        float bv = bias[j0 + ty * 8 + ii];
        float* p = &g_xproj[((size_t)t * R4 + r) * Bdim + b0];
        float4 v0 = {acc[ii][0] + bv, acc[ii][1] + bv, acc[ii][2] + bv, acc[ii][3] + bv};
        float4 v1 = {acc[ii][4] + bv, acc[ii][5] + bv, acc[ii][6] + bv, acc[ii][7] + bv};
        *(float4*)p       = v0;
        *(float4*)(p + 4) = v1;
    }
}

// ---------------------------------------------------------------------------
__device__ __forceinline__ void gridbar(unsigned &gen) {
    __syncthreads();
    if (threadIdx.x == 0) {
        __threadfence();
        if (atomicAdd(&g_count, 1u) == NBLK - 1) {
            g_count = 0u;
            __threadfence();
            atomicExch(&g_gen, gen + 1u);
        } else {
            for (long i = 0; i < 200000000L; i++)
                if (*((volatile unsigned*)&g_gen) != gen) break;
        }
        __threadfence();
    }
    gen++;
    __syncthreads();
}

// ---------------------------------------------------------------------------
// Persistent recurrence: 128 blocks = 32 rowblocks (M=128) x 4 K-splits (K=256).
// GEMM on mma.sync bf16 (3-term split). Reduce phase fuses gates; c in regs.
// ---------------------------------------------------------------------------
__global__ void __launch_bounds__(256, 1)
recur_tc(void)
{
    extern __shared__ __nv_bfloat16 sB[];   // [2][16*1024] bf16 = 64 KB
    const u32 sb = s2u(sB);

    const int bid  = blockIdx.x;
    const int tid  = threadIdx.x;
    const int ks   = bid & 3;           // K-split
    const int rb   = bid >> 2;          // rowblock 0..31
    const int w    = tid >> 5;
    const int lane = tid & 31;
    const int g    = lane >> 2;
    const int tg   = lane & 3;
    const int rt   = rb * 8 + w;        // rowtile 0..255

    // reduce-phase mapping: this thread owns (jj, bb) and (jj, bb+1) forever
    const int p0 = bid * 512 + tid * 2;
    const int jj = p0 >> 6;
    const int bb = p0 & 63;
    float cst0 = 0.0f, cst1 = 0.0f;

    unsigned gen = 0;

    for (int t = 0; t < Tdim; t++) {
        const int buf  = t & 1;
        const int nbuf = buf ^ 1;

        // ---- stage B (h fragments, this block's K-slice) into smem --------
        {
            const char* s0 = (const char*)(g_hfrag[buf][0] + ks * 16384);
            const char* s1 = (const char*)(g_hfrag[buf][1] + ks * 16384);
#pragma unroll
            for (int i = 0; i < 8; i++) {
                int e = tid + i * 256;              // 0..2047 16B units
                cpa16(sb + e * 16,         s0 + (size_t)e * 16);
                cpa16(sb + 32768 + e * 16, s1 + (size_t)e * 16);
            }
            cpa_commit();
        }

        // ---- prefetch xproj for reduce phase (hides DRAM latency) ---------
        float2 xp[4];
#pragma unroll
        for (int gate = 0; gate < 4; gate++)
            xp[gate] = __ldg((const float2*)
                &g_xproj[((size_t)t * R4 + gate * 1024 + jj) * Bdim + bb]);

        cpa_wait<0>();
        __syncthreads();

        // ---- GEMM: D[128x64] partial for K-slice --------------------------
        float c[8][4];
#pragma unroll
        for (int nt = 0; nt < 8; nt++)
#pragma unroll
            for (int q = 0; q < 4; q++) c[nt][q] = 0.0f;

        for (int ktl = 0; ktl < 16; ktl++) {
            int ktg = ks * 16 + ktl;
            uint4 ahi = g_Wfrag[((size_t)(0 * 256 + rt) * 64 + ktg) * 32 + lane];
            uint4 alo = g_Wfrag[((size_t)(1 * 256 + rt) * 64 + ktg) * 32 + lane];
#pragma unroll
            for (int nt = 0; nt < 8; nt++) {
                int n   = nt * 8 + g;
                int off = ktl * 1024 + n * 16 + tg * 2;
                u32 bh0 = *(const u32*)&sB[off];
                u32 bh1 = *(const u32*)&sB[off + 8];
                u32 bl0 = *(const u32*)&sB[16384 + off];
                u32 bl1 = *(const u32*)&sB[16384 + off + 8];
                MMA(c[nt], ahi, bh0, bh1);
                MMA(c[nt], ahi, bl0, bl1);
                MMA(c[nt], alo, bh0, bh1);
            }
        }

        // ---- store partials ----------------------------------------------
        {
            int R0 = rt * 16 + g;
#pragma unroll
            for (int nt = 0; nt < 8; nt++) {
                int bcol = nt * 8 + tg * 2;
                float2 v0 = {c[nt][0], c[nt][1]};
                float2 v1 = {c[nt][2], c[nt][3]};
                *(float2*)&g_partial[((size_t)ks * R4 + R0)     * Bdim + bcol] = v0;
                *(float2*)&g_partial[((size_t)ks * R4 + R0 + 8) * Bdim + bcol] = v1;
            }
        }

        gridbar(gen);

        // ---- reduce + gates + state update --------------------------------
        {
            float2 acc[4];
#pragma unroll
            for (int gate = 0; gate < 4; gate++) {
                acc[gate] = xp[gate];
#pragma unroll
                for (int ksp = 0; ksp < KSPLIT; ksp++) {
                    float2 pv = __ldcg((const float2*)
                        &g_partial[((size_t)ksp * R4 + gate * 1024 + jj) * Bdim + bb]);
                    acc[gate].x += pv.x;
                    acc[gate].y += pv.y;
                }
            }

            float f0  = 1.0f / (1.0f + __expf(-acc[0].x));
            float f1  = 1.0f / (1.0f + __expf(-acc[0].y));
            float i0  = 1.0f / (1.0f + __expf(-acc[1].x));
            float i1  = 1.0f / (1.0f + __expf(-acc[1].y));
            float ct0 = tanhf(acc[2].x);
            float ct1 = tanhf(acc[2].y);
            float o0  = 1.0f / (1.0f + __expf(-acc[3].x));
            float o1  = 1.0f / (1.0f + __expf(-acc[3].y));

            cst0 = f0 * cst0 + i0 * ct0;
            cst1 = f1 * cst1 + i1 * ct1;
            float h0 = o0 * tanhf(cst0);
            float h1 = o1 * tanhf(cst1);

            __nv_bfloat16 hh0 = __float2bfloat16(h0);
            __nv_bfloat16 hh1 = __float2bfloat16(h1);
            __nv_bfloat16 hl0 = __float2bfloat16(h0 - __bfloat162float(hh0));
            __nv_bfloat16 hl1 = __float2bfloat16(h1 - __bfloat162float(hh1));

            int idx0 = ((jj >> 4) * 64 + bb) * 16 + (jj & 15);
            g_hfrag[nbuf][0][idx0]      = hh0;
            g_hfrag[nbuf][0][idx0 + 16] = hh1;
            g_hfrag[nbuf][1][idx0]      = hl0;
            g_hfrag[nbuf][1][idx0 + 16] = hl1;

            if (t == Tdim - 1) {
                g_h[jj * Bdim + bb]     = h0;
                g_h[jj * Bdim + bb + 1] = h1;
            }
        }

        gridbar(gen);   // h_t published before any block stages step t+1's B
    }
}

// ---------------------------------------------------------------------------
// Final FC: out[b][s] = sum_k h_T[k][b] * fc_w[s][k] + fc_b[s]
// ---------------------------------------------------------------------------
__global__ void __launch_bounds__(512)
fc_kernel(const float* __restrict__ fc_w, const float* __restrict__ fc_b,
          float* __restrict__ out)
{
    __shared__ float hs[128 * 64];
    __shared__ float ws[8 * 128];

    const float* __restrict__ hT = g_h;
    int tid = threadIdx.x;
    int b   = tid & 63;
    int sl  = tid >> 6;
    int s   = blockIdx.x * 8 + sl;

    float acc = 0.0f;
    for (int k0 = 0; k0 < Hdim; k0 += 128) {
        __syncthreads();
#pragma unroll
        for (int i2 = 0; i2 < 4; i2++) {
            int e = tid + i2 * 512;
            *(float4*)&hs[e * 4] = *(const float4*)&hT[k0 * Bdim + e * 4];
        }
#pragma unroll
        for (int i2 = 0; i2 < 2; i2++) {
            int e    = tid + i2 * 512;
            int srow = e >> 7, kk = e & 127;
            ws[srow * 128 + kk] = fc_w[(size_t)(blockIdx.x * 8 + srow) * Hdim + k0 + kk];
        }
        __syncthreads();
#pragma unroll 16
        for (int kk = 0; kk < 128; kk++)
            acc += hs[kk * 64 + b] * ws[sl * 128 + kk];
    }
    out[b * Sdim + s] = acc + fc_b[s];
}

// ---------------------------------------------------------------------------
extern "C" void kernel_launch(void* const* d_in, const int* in_sizes, int n_in,
                              void* d_out, int out_size)
{
    const float* x   = (const float*)d_in[0];
    const float* Wf  = (const float*)d_in[1];
    const float* bf  = (const float*)d_in[2];
    const float* Wi  = (const float*)d_in[3];
    const float* bi  = (const float*)d_in[4];
    const float* Wc  = (const float*)d_in[5];
    const float* bc  = (const float*)d_in[6];
    const float* Wo  = (const float*)d_in[7];
    const float* bo  = (const float*)d_in[8];
    const float* fcw = (const float*)d_in[9];
    const float* fcb = (const float*)d_in[10];
    float* out = (float*)d_out;

    cudaFuncSetAttribute(recur_tc, cudaFuncAttributeMaxDynamicSharedMemorySize,
                         65536);

    init_kernel<<<(64 * 1024 + 255) / 256, 256>>>();
    prepack_kernel<<<2 * 256 * 64 * 32 / 256, 256>>>(Wf, Wi, Wc, Wo);

    dim3 gx(256, 32);
    xproj_kernel<<<gx, 256>>>(x, Wf, bf, Wi, bi, Wc, bc, Wo, bo);

    recur_tc<<<NBLK, 256, 65536>>>();

    fc_kernel<<<64, 512>>>(fcw, fcb, out);
}

// round 7
// speedup vs baseline: 2.3306x; 1.1970x over previous
#include <cuda_runtime.h>
#include <cuda_bf16.h>
#include <math.h>
#include <stdint.h>

#define Bdim 64
#define Tdim 512
#define Idim 512
#define Hdim 1024
#define Sdim 512
#define R4   4096
#define KSPLIT 4
#define NBLK 128     // persistent blocks (<=148 SMs)

typedef unsigned long long u64;
typedef unsigned int u32;

// ---------------- static device scratch ------------------------------------
__device__ float g_xproj[(size_t)Tdim * R4 * Bdim];   // [t][r][b], r = gate*1024+j
__device__ uint4 g_Wfrag[2 * 256 * 64 * 32];          // recur W: [term][rt][ktile][lane]
__device__ uint4 g_WXfrag[2 * 256 * 32 * 32];         // xproj W: [term][rt][ktile][lane]
__device__ __nv_bfloat16 g_xbf[2][(size_t)Tdim * Bdim * Idim];  // [term][(t*64+b)*512+k]
__device__ __nv_bfloat16 g_hfrag[2][2][64 * 1024];    // [buf][term][(kt*64+n)*16+k]
__device__ float g_partial[(size_t)KSPLIT * R4 * Bdim];
__device__ float g_h[Hdim * Bdim];                    // final h, [j][b]
__device__ unsigned g_count, g_gen;

// ---------------- helpers ---------------------------------------------------
__device__ __forceinline__ u32 s2u(const void* p) {
    u32 a;
    asm("{ .reg .u64 t; cvta.to.shared.u64 t, %1; cvt.u32.u64 %0, t; }"
        : "=r"(a) : "l"(p));
    return a;
}
__device__ __forceinline__ void cpa16(u32 dst, const void* src) {
    asm volatile("cp.async.cg.shared.global [%0], [%1], 16;"
                 :: "r"(dst), "l"(src) : "memory");
}
__device__ __forceinline__ void cpa_commit() {
    asm volatile("cp.async.commit_group;" ::: "memory");
}
template<int N> __device__ __forceinline__ void cpa_wait() {
    asm volatile("cp.async.wait_group %0;" :: "n"(N) : "memory");
}

#define MMA(c, a, b0, b1)                                                    \
    asm volatile("mma.sync.aligned.m16n8k16.row.col.f32.bf16.bf16.f32 "      \
        "{%0,%1,%2,%3}, {%4,%5,%6,%7}, {%8,%9}, {%0,%1,%2,%3};"              \
        : "+f"((c)[0]), "+f"((c)[1]), "+f"((c)[2]), "+f"((c)[3])             \
        : "r"((a).x), "r"((a).y), "r"((a).z), "r"((a).w), "r"(b0), "r"(b1))

// ---------------------------------------------------------------------------
__global__ void init_kernel() {
    int i = blockIdx.x * blockDim.x + threadIdx.x;
    if (i < 64 * 1024) {
        __nv_bfloat16 z = __float2bfloat16(0.0f);
        g_hfrag[0][0][i] = z; g_hfrag[0][1][i] = z;
        g_hfrag[1][0][i] = z; g_hfrag[1][1][i] = z;
    }
    if (i == 0) { g_count = 0u; g_gen = 0u; }
}

// ---------------------------------------------------------------------------
__device__ __forceinline__ u32 pk2(float w0, float w1, int term) {
    __nv_bfloat16 h0 = __float2bfloat16(w0), h1 = __float2bfloat16(w1);
    if (term) {
        h0 = __float2bfloat16(w0 - __bfloat162float(h0));
        h1 = __float2bfloat16(w1 - __bfloat162float(h1));
    }
    u32 lo = (u32)*(unsigned short*)&h0;
    u32 hi = (u32)*(unsigned short*)&h1;
    return (hi << 16) | lo;
}

// Pre-pack W_h (cols 0..1023) into mma A-fragment order (recurrence).
__global__ void prepack_kernel(const float* __restrict__ Wf, const float* __restrict__ Wi,
                               const float* __restrict__ Wc, const float* __restrict__ Wo)
{
    int idx = blockIdx.x * 256 + threadIdx.x;       // 0 .. 2*256*64*32-1
    int term = idx >> 19;
    int q    = idx & 0x7FFFF;
    int rt   = q >> 11;                             // 0..255
    int kt   = (q >> 5) & 63;                       // 0..63
    int lane = q & 31;
    int g = lane >> 2, tg = lane & 3;

    int R0   = rt * 16 + g;
    int gate = R0 >> 10;
    int j    = R0 & 1023;
    const float* W = (gate == 0) ? Wf : (gate == 1) ? Wi : (gate == 2) ? Wc : Wo;
    const float* r0 = W + (size_t)j * 1536;         // h-part = cols 0..1023
    const float* r1 = W + (size_t)(j + 8) * 1536;
    int k0 = kt * 16 + tg * 2;

    uint4 v;
    v.x = pk2(r0[k0],     r0[k0 + 1], term);
    v.y = pk2(r1[k0],     r1[k0 + 1], term);
    v.z = pk2(r0[k0 + 8], r0[k0 + 9], term);
    v.w = pk2(r1[k0 + 8], r1[k0 + 9], term);
    g_Wfrag[idx] = v;
}

// Pre-pack W_x (cols 1024..1535) into mma A-fragment order (xproj).
__global__ void prepack_wx_kernel(const float* __restrict__ Wf, const float* __restrict__ Wi,
                                  const float* __restrict__ Wc, const float* __restrict__ Wo)
{
    int idx = blockIdx.x * 256 + threadIdx.x;       // 0 .. 2*256*32*32-1
    int term = idx >> 18;
    int q    = idx & 0x3FFFF;
    int rt   = q >> 10;                             // 0..255
    int kt   = (q >> 5) & 31;                       // 0..31
    int lane = q & 31;
    int g = lane >> 2, tg = lane & 3;

    int R0   = rt * 16 + g;
    int gate = R0 >> 10;
    int j    = R0 & 1023;
    const float* W = (gate == 0) ? Wf : (gate == 1) ? Wi : (gate == 2) ? Wc : Wo;
    const float* r0 = W + (size_t)j * 1536 + 1024;  // x-part = cols 1024..1535
    const float* r1 = W + (size_t)(j + 8) * 1536 + 1024;
    int k0 = kt * 16 + tg * 2;

    uint4 v;
    v.x = pk2(r0[k0],     r0[k0 + 1], term);
    v.y = pk2(r1[k0],     r1[k0 + 1], term);
    v.z = pk2(r0[k0 + 8], r0[k0 + 9], term);
    v.w = pk2(r1[k0 + 8], r1[k0 + 9], term);
    g_WXfrag[idx] = v;
}

// ---------------------------------------------------------------------------
// Convert x [b][t][k] fp32 -> g_xbf[term][(t*64+b)*512+k] bf16 hi/lo.
// ---------------------------------------------------------------------------
__global__ void convert_x_kernel(const float* __restrict__ x)
{
    size_t q = (size_t)blockIdx.x * 256 + threadIdx.x;   // 4 elements each
    size_t base = q * 4;                                 // linear over [b][t][k]
    if (base >= (size_t)Bdim * Tdim * Idim) return;
    int k = (int)(base & 511);
    size_t rest = base >> 9;
    int t = (int)(rest & 511);
    int b = (int)(rest >> 9);

    float4 v = *(const float4*)&x[base];
    uint2 hi, lo;
    hi.x = pk2(v.x, v.y, 0); hi.y = pk2(v.z, v.w, 0);
    lo.x = pk2(v.x, v.y, 1); lo.y = pk2(v.z, v.w, 1);
    size_t n = (size_t)t * 64 + b;
    *(uint2*)&g_xbf[0][n * 512 + k] = hi;
    *(uint2*)&g_xbf[1][n * 512 + k] = lo;
}

// ---------------------------------------------------------------------------
// xproj (tensor): xproj[t][r][b] = b_g + sum_k x[b,t,k]*W[r][1024+k].
// Block tile M=128 (rb) x N=128 (cb, n = t*64+b), K=512 chunked by 64.
// 8 warps, one rowtile each, 16 n-tiles; bf16 3-term split.
// ---------------------------------------------------------------------------
__global__ void __launch_bounds__(256, 1)
xproj_tc(const float* __restrict__ bf, const float* __restrict__ bi,
         const float* __restrict__ bc, const float* __restrict__ bo)
{
    extern __shared__ __nv_bfloat16 sX[];   // 2 bufs x [term][4 ktl][128 n][16 k] = 64 KB
    const u32 sb = s2u(sX);

    const int cb   = blockIdx.x;        // 0..255
    const int rb   = blockIdx.y;        // 0..31
    const int tid  = threadIdx.x;
    const int w    = tid >> 5;
    const int lane = tid & 31;
    const int g    = lane >> 2;
    const int tg   = lane & 3;
    const int rtg  = rb * 8 + w;        // rowtile 0..255

    // bias for this thread's two rows
    const int R0 = rtg * 16 + g;
    const int gate = R0 >> 10, jb = R0 & 1023;
    const float* bias = (gate == 0) ? bf : (gate == 1) ? bi : (gate == 2) ? bc : bo;
    const float bv0 = bias[jb];
    const float bv1 = bias[jb + 8];

    float c[16][4];
#pragma unroll
    for (int nt = 0; nt < 16; nt++)
#pragma unroll
        for (int q = 0; q < 4; q++) c[nt][q] = 0.0f;

    // ---- stage chunk into smem buffer s: 2048 16B units --------------------
    auto stage = [&](int chunk, int s) {
#pragma unroll
        for (int i = 0; i < 8; i++) {
            int e = tid + i * 256;              // 0..2047
            int term = e >> 10;
            int u = e & 1023;
            int n = u >> 3, seg = u & 7;
            int ktl = seg >> 1, rem8 = (seg & 1) * 8;
            u32 dst = sb + (u32)(s * 16384 + term * 8192 + ktl * 2048 + n * 16 + rem8) * 2;
            const __nv_bfloat16* src = g_xbf[term] +
                ((size_t)(cb * 128 + n) * 512 + chunk * 64 + seg * 8);
            cpa16(dst, src);
        }
        cpa_commit();
    };

    stage(0, 0);
    for (int ch = 0; ch < 8; ch++) {
        int s = ch & 1;
        if (ch < 7) { stage(ch + 1, s ^ 1); cpa_wait<1>(); }
        else        { cpa_wait<0>(); }
        __syncthreads();

#pragma unroll
        for (int ktl = 0; ktl < 4; ktl++) {
            int ktg = ch * 4 + ktl;
            uint4 ahi = g_WXfrag[((size_t)(0 * 256 + rtg) * 32 + ktg) * 32 + lane];
            uint4 alo = g_WXfrag[((size_t)(1 * 256 + rtg) * 32 + ktg) * 32 + lane];
            const __nv_bfloat16* bufh = sX + s * 16384 + 0 * 8192 + ktl * 2048;
            const __nv_bfloat16* bufl = sX + s * 16384 + 1 * 8192 + ktl * 2048;
#pragma unroll
            for (int nt = 0; nt < 16; nt++) {
                int off = (nt * 8 + g) * 16 + tg * 2;
                u32 bh0 = *(const u32*)&bufh[off];
                u32 bh1 = *(const u32*)&bufh[off + 8];
                u32 bl0 = *(const u32*)&bufl[off];
                u32 bl1 = *(const u32*)&bufl[off + 8];
                MMA(c[nt], ahi, bh0, bh1);
                MMA(c[nt], ahi, bl0, bl1);
                MMA(c[nt], alo, bh0, bh1);
            }
        }
        __syncthreads();
    }

    // ---- epilogue: bias + store to g_xproj[t][r][b] ------------------------
#pragma unroll
    for (int nt = 0; nt < 16; nt++) {
        int n = cb * 128 + nt * 8 + tg * 2;
        int t = n >> 6, b = n & 63;
        float2 v0 = {c[nt][0] + bv0, c[nt][1] + bv0};
        float2 v1 = {c[nt][2] + bv1, c[nt][3] + bv1};
        *(float2*)&g_xproj[((size_t)t * R4 + R0)     * Bdim + b] = v0;
        *(float2*)&g_xproj[((size_t)t * R4 + R0 + 8) * Bdim + b] = v1;
    }
}

// ---------------------------------------------------------------------------
__device__ __forceinline__ void gridbar(unsigned &gen) {
    __syncthreads();
    if (threadIdx.x == 0) {
        __threadfence();
        if (atomicAdd(&g_count, 1u) == NBLK - 1) {
            g_count = 0u;
            __threadfence();
            atomicExch(&g_gen, gen + 1u);
        } else {
            for (long i = 0; i < 200000000L; i++)
                if (*((volatile unsigned*)&g_gen) != gen) break;
        }
        __threadfence();
    }
    gen++;
    __syncthreads();
}

// ---------------------------------------------------------------------------
// Persistent recurrence: 128 blocks = 32 rowblocks (M=128) x 4 K-splits (K=256).
// (unchanged from the passing R6 kernel)
// ---------------------------------------------------------------------------
__global__ void __launch_bounds__(256, 1)
recur_tc(void)
{
    extern __shared__ __nv_bfloat16 sB[];   // [2][16*1024] bf16 = 64 KB
    const u32 sb = s2u(sB);

    const int bid  = blockIdx.x;
    const int tid  = threadIdx.x;
    const int ks   = bid & 3;           // K-split
    const int rb   = bid >> 2;          // rowblock 0..31
    const int w    = tid >> 5;
    const int lane = tid & 31;
    const int g    = lane >> 2;
    const int tg   = lane & 3;
    const int rt   = rb * 8 + w;        // rowtile 0..255

    const int p0 = bid * 512 + tid * 2;
    const int jj = p0 >> 6;
    const int bb = p0 & 63;
    float cst0 = 0.0f, cst1 = 0.0f;

    unsigned gen = 0;

    for (int t = 0; t < Tdim; t++) {
        const int buf  = t & 1;
        const int nbuf = buf ^ 1;

        {
            const char* s0 = (const char*)(g_hfrag[buf][0] + ks * 16384);
            const char* s1 = (const char*)(g_hfrag[buf][1] + ks * 16384);
#pragma unroll
            for (int i = 0; i < 8; i++) {
                int e = tid + i * 256;
                cpa16(sb + e * 16,         s0 + (size_t)e * 16);
                cpa16(sb + 32768 + e * 16, s1 + (size_t)e * 16);
            }
            cpa_commit();
        }

        float2 xp[4];
#pragma unroll
        for (int gate = 0; gate < 4; gate++)
            xp[gate] = __ldg((const float2*)
                &g_xproj[((size_t)t * R4 + gate * 1024 + jj) * Bdim + bb]);

        cpa_wait<0>();
        __syncthreads();

        float c[8][4];
#pragma unroll
        for (int nt = 0; nt < 8; nt++)
#pragma unroll
            for (int q = 0; q < 4; q++) c[nt][q] = 0.0f;

        for (int ktl = 0; ktl < 16; ktl++) {
            int ktg = ks * 16 + ktl;
            uint4 ahi = g_Wfrag[((size_t)(0 * 256 + rt) * 64 + ktg) * 32 + lane];
            uint4 alo = g_Wfrag[((size_t)(1 * 256 + rt) * 64 + ktg) * 32 + lane];
#pragma unroll
            for (int nt = 0; nt < 8; nt++) {
                int n   = nt * 8 + g;
                int off = ktl * 1024 + n * 16 + tg * 2;
                u32 bh0 = *(const u32*)&sB[off];
                u32 bh1 = *(const u32*)&sB[off + 8];
                u32 bl0 = *(const u32*)&sB[16384 + off];
                u32 bl1 = *(const u32*)&sB[16384 + off + 8];
                MMA(c[nt], ahi, bh0, bh1);
                MMA(c[nt], ahi, bl0, bl1);
                MMA(c[nt], alo, bh0, bh1);
            }
        }

        {
            int R0 = rt * 16 + g;
#pragma unroll
            for (int nt = 0; nt < 8; nt++) {
                int bcol = nt * 8 + tg * 2;
                float2 v0 = {c[nt][0], c[nt][1]};
                float2 v1 = {c[nt][2], c[nt][3]};
                *(float2*)&g_partial[((size_t)ks * R4 + R0)     * Bdim + bcol] = v0;
                *(float2*)&g_partial[((size_t)ks * R4 + R0 + 8) * Bdim + bcol] = v1;
            }
        }

        gridbar(gen);

        {
            float2 acc[4];
#pragma unroll
            for (int gate = 0; gate < 4; gate++) {
                acc[gate] = xp[gate];
#pragma unroll
                for (int ksp = 0; ksp < KSPLIT; ksp++) {
                    float2 pv = __ldcg((const float2*)
                        &g_partial[((size_t)ksp * R4 + gate * 1024 + jj) * Bdim + bb]);
                    acc[gate].x += pv.x;
                    acc[gate].y += pv.y;
                }
            }

            float f0  = 1.0f / (1.0f + __expf(-acc[0].x));
            float f1  = 1.0f / (1.0f + __expf(-acc[0].y));
            float i0  = 1.0f / (1.0f + __expf(-acc[1].x));
            float i1  = 1.0f / (1.0f + __expf(-acc[1].y));
            float ct0 = tanhf(acc[2].x);
            float ct1 = tanhf(acc[2].y);
            float o0  = 1.0f / (1.0f + __expf(-acc[3].x));
            float o1  = 1.0f / (1.0f + __expf(-acc[3].y));

            cst0 = f0 * cst0 + i0 * ct0;
            cst1 = f1 * cst1 + i1 * ct1;
            float h0 = o0 * tanhf(cst0);
            float h1 = o1 * tanhf(cst1);

            __nv_bfloat16 hh0 = __float2bfloat16(h0);
            __nv_bfloat16 hh1 = __float2bfloat16(h1);
            __nv_bfloat16 hl0 = __float2bfloat16(h0 - __bfloat162float(hh0));
            __nv_bfloat16 hl1 = __float2bfloat16(h1 - __bfloat162float(hh1));

            int idx0 = ((jj >> 4) * 64 + bb) * 16 + (jj & 15);
            g_hfrag[nbuf][0][idx0]      = hh0;
            g_hfrag[nbuf][0][idx0 + 16] = hh1;
            g_hfrag[nbuf][1][idx0]      = hl0;
            g_hfrag[nbuf][1][idx0 + 16] = hl1;

            if (t == Tdim - 1) {
                g_h[jj * Bdim + bb]     = h0;
                g_h[jj * Bdim + bb + 1] = h1;
            }
        }

        gridbar(gen);
    }
}

// ---------------------------------------------------------------------------
// Final FC: out[b][s] = sum_k h_T[k][b] * fc_w[s][k] + fc_b[s]
// ---------------------------------------------------------------------------
__global__ void __launch_bounds__(512)
fc_kernel(const float* __restrict__ fc_w, const float* __restrict__ fc_b,
          float* __restrict__ out)
{
    __shared__ float hs[128 * 64];
    __shared__ float ws[8 * 128];

    const float* __restrict__ hT = g_h;
    int tid = threadIdx.x;
    int b   = tid & 63;
    int sl  = tid >> 6;
    int s   = blockIdx.x * 8 + sl;

    float acc = 0.0f;
    for (int k0 = 0; k0 < Hdim; k0 += 128) {
        __syncthreads();
#pragma unroll
        for (int i2 = 0; i2 < 4; i2++) {
            int e = tid + i2 * 512;
            *(float4*)&hs[e * 4] = *(const float4*)&hT[k0 * Bdim + e * 4];
        }
#pragma unroll
        for (int i2 = 0; i2 < 2; i2++) {
            int e    = tid + i2 * 512;
            int srow = e >> 7, kk = e & 127;
            ws[srow * 128 + kk] = fc_w[(size_t)(blockIdx.x * 8 + srow) * Hdim + k0 + kk];
        }
        __syncthreads();
#pragma unroll 16
        for (int kk = 0; kk < 128; kk++)
            acc += hs[kk * 64 + b] * ws[sl * 128 + kk];
    }
    out[b * Sdim + s] = acc + fc_b[s];
}

// ---------------------------------------------------------------------------
extern "C" void kernel_launch(void* const* d_in, const int* in_sizes, int n_in,
                              void* d_out, int out_size)
{
    const float* x   = (const float*)d_in[0];
    const float* Wf  = (const float*)d_in[1];
    const float* bf  = (const float*)d_in[2];
    const float* Wi  = (const float*)d_in[3];
    const float* bi  = (const float*)d_in[4];
    const float* Wc  = (const float*)d_in[5];
    const float* bc  = (const float*)d_in[6];
    const float* Wo  = (const float*)d_in[7];
    const float* bo  = (const float*)d_in[8];
    const float* fcw = (const float*)d_in[9];
    const float* fcb = (const float*)d_in[10];
    float* out = (float*)d_out;

    cudaFuncSetAttribute(recur_tc, cudaFuncAttributeMaxDynamicSharedMemorySize, 65536);
    cudaFuncSetAttribute(xproj_tc, cudaFuncAttributeMaxDynamicSharedMemorySize, 65536);

    init_kernel<<<(64 * 1024 + 255) / 256, 256>>>();
    prepack_kernel<<<2 * 256 * 64 * 32 / 256, 256>>>(Wf, Wi, Wc, Wo);
    prepack_wx_kernel<<<2 * 256 * 32 * 32 / 256, 256>>>(Wf, Wi, Wc, Wo);
    convert_x_kernel<<<(Bdim * Tdim * Idim / 4 + 255) / 256, 256>>>(x);

    dim3 gx(256, 32);
    xproj_tc<<<gx, 256, 65536>>>(bf, bi, bc, bo);

    recur_tc<<<NBLK, 256, 65536>>>();

    fc_kernel<<<64, 512>>>(fcw, fcb, out);
}